// round 12
// baseline (speedup 1.0000x reference)
#include <cuda_runtime.h>
#include <cuda_fp16.h>
#include <math_constants.h>

// ---------------------------------------------------------------------------
// Quantization4bit, single persistent kernel:
//   phase 1: per-block min/max partials (grid-stride, float4 __ldcg, unroll-4)
//   grid barrier: monotonic counter/epoch (replay-safe)
//   phase 2: affine normalize + nearest-codebook via a 256-cell LUT of
//            half2(c_lo, c_hi), replicated x32 at s[cell*32+lane] so every
//            gather is bank-conflict-free regardless of data distribution.
//            Copy-based build (256 chain evals + lane-rotated replication).
//            Midpoint recomputed as 0.5f*(f32(lo)+f32(hi)) -- identical fp32
//            ops/inputs as the reference chain => bit-exact
//            (fp32 |.| argmin, first-min tie-break).
// 740 blocks x 256 thr, 5 blocks/SM co-resident (launch_bounds, 32KB smem
// x5 = 160KB/SM <= 228KB) => spin barrier safe.
// ---------------------------------------------------------------------------

#define MAX_CB 16
#define NBLK 740
#define NTHR 256
#define NCELL 256

__device__ float g_pmin[NBLK];
__device__ float g_pmax[NBLK];
__device__ float g_final_min;
__device__ float g_final_max;
__device__ unsigned g_counter = 0;   // monotonic arrivals (never reset)
__device__ unsigned g_release = 0;   // monotonic release epoch

__device__ __forceinline__ int cell_of(float xn) {
    float u = fmaf(xn, (float)(NCELL / 2), (float)(NCELL / 2));  // >= 0 by construction
    u = fminf(u, (float)(NCELL - 1));
    return (int)u;
}

__device__ __forceinline__ float lut_pick(unsigned e, float xn) {
    float lo = __half2float(__ushort_as_half((unsigned short)(e & 0xFFFFu)));
    float hi = __half2float(__ushort_as_half((unsigned short)(e >> 16)));
    float mid = 0.5f * (lo + hi);   // exact same computation as reference mid[]
    // strict > : exact-midpoint ties go to the LOWER index,
    // matching argmin's first-minimum tie-break.
    return (xn > mid) ? hi : lo;
}

__device__ __forceinline__ void mm4(float4 v, float& mn, float& mx) {
    mn = fminf(mn, fminf(fminf(v.x, v.y), fminf(v.z, v.w)));
    mx = fmaxf(mx, fmaxf(fmaxf(v.x, v.y), fmaxf(v.z, v.w)));
}

__device__ __forceinline__ float4 quant4(float4 v, float xmin, float inv,
                                         const unsigned* s_tbl, int lane) {
    float a[4] = {v.x, v.y, v.z, v.w};
    float r[4];
    #pragma unroll
    for (int k = 0; k < 4; k++) {
        float xn = fmaf((a[k] - xmin) * inv, 2.0f, -1.0f);
        unsigned e = s_tbl[(cell_of(xn) << 5) | lane];   // bank == lane
        r[k] = lut_pick(e, xn);
    }
    return make_float4(r[0], r[1], r[2], r[3]);
}

__global__ void __launch_bounds__(NTHR, 5)
q4_fused_kernel(const float4* __restrict__ x,
                const float* __restrict__ cb, int n_cb,
                float4* __restrict__ out, int n4) {
    __shared__ unsigned s_tbl[NCELL * 32];   // x32 replicated, bank == lane
    __shared__ float s_red[NTHR / 32];
    __shared__ float s_red2[NTHR / 32];
    __shared__ unsigned s_epoch;
    __shared__ int s_last;

    const int tid = blockIdx.x * NTHR + threadIdx.x;
    const int stride = NBLK * NTHR;
    const int lane = threadIdx.x & 31;
    const int warp = threadIdx.x >> 5;

    // ---------------- phase 1: local min/max (unroll 4, .cg loads) --------
    float lmin = CUDART_INF_F;
    float lmax = -CUDART_INF_F;

    int i = tid;
    for (; i + 3 * stride < n4; i += 4 * stride) {
        float4 v0 = __ldcg(&x[i]);
        float4 v1 = __ldcg(&x[i + stride]);
        float4 v2 = __ldcg(&x[i + 2 * stride]);
        float4 v3 = __ldcg(&x[i + 3 * stride]);
        mm4(v0, lmin, lmax);
        mm4(v1, lmin, lmax);
        mm4(v2, lmin, lmax);
        mm4(v3, lmin, lmax);
    }
    for (; i < n4; i += stride) {
        float4 v = __ldcg(&x[i]);
        mm4(v, lmin, lmax);
    }

    #pragma unroll
    for (int o = 16; o > 0; o >>= 1) {
        lmin = fminf(lmin, __shfl_xor_sync(0xFFFFFFFFu, lmin, o));
        lmax = fmaxf(lmax, __shfl_xor_sync(0xFFFFFFFFu, lmax, o));
    }
    if (lane == 0) { s_red[warp] = lmin; s_red2[warp] = lmax; }
    __syncthreads();

    if (threadIdx.x == 0) {
        float bmin = s_red[0], bmax = s_red2[0];
        #pragma unroll
        for (int w = 1; w < NTHR / 32; w++) {
            bmin = fminf(bmin, s_red[w]);
            bmax = fmaxf(bmax, s_red2[w]);
        }
        g_pmin[blockIdx.x] = bmin;
        g_pmax[blockIdx.x] = bmax;
        __threadfence();
        unsigned old = atomicAdd(&g_counter, 1u);
        s_epoch = old / NBLK;
        s_last = ((old % NBLK) == NBLK - 1);
    }
    __syncthreads();

    const unsigned epoch = s_epoch;

    if (s_last) {
        float bmin = CUDART_INF_F, bmax = -CUDART_INF_F;
        for (int j = threadIdx.x; j < NBLK; j += NTHR) {
            bmin = fminf(bmin, g_pmin[j]);
            bmax = fmaxf(bmax, g_pmax[j]);
        }
        #pragma unroll
        for (int o = 16; o > 0; o >>= 1) {
            bmin = fminf(bmin, __shfl_xor_sync(0xFFFFFFFFu, bmin, o));
            bmax = fmaxf(bmax, __shfl_xor_sync(0xFFFFFFFFu, bmax, o));
        }
        if (lane == 0) { s_red[warp] = bmin; s_red2[warp] = bmax; }
        __syncthreads();
        if (threadIdx.x == 0) {
            float fmn = s_red[0], fmx = s_red2[0];
            #pragma unroll
            for (int w = 1; w < NTHR / 32; w++) {
                fmn = fminf(fmn, s_red[w]);
                fmx = fmaxf(fmx, s_red2[w]);
            }
            g_final_min = fmn;
            g_final_max = fmx;
            __threadfence();
            atomicAdd(&g_release, 1u);
        }
        __syncthreads();
    } else {
        if (threadIdx.x == 0) {
            while (*((volatile unsigned*)&g_release) < epoch + 1u)
                __nanosleep(64);
        }
        __syncthreads();
    }
    __threadfence();  // acquire for g_final_min/max

    const float xmin = g_final_min;
    const float xmax = g_final_max;
    const float inv = 1.0f / (xmax - xmin);

    // ------- build the x32-replicated 4B/cell LUT (copy-based, cheap) -----
    {
        float c[MAX_CB];
        #pragma unroll
        for (int k = 0; k < MAX_CB; k++)
            c[k] = (k < n_cb) ? cb[k] : CUDART_INF_F;
        float mid[MAX_CB - 1];
        #pragma unroll
        for (int j = 0; j < MAX_CB - 1; j++)
            mid[j] = (j + 1 < n_cb) ? 0.5f * (c[j] + c[j + 1]) : CUDART_INF_F;

        // each thread owns exactly one cell (NTHR == NCELL)
        int cell = threadIdx.x;
        float xc = ((float)cell + 0.5f) * (2.0f / NCELL) - 1.0f;
        float val = c[0];
        #pragma unroll
        for (int j = 0; j < MAX_CB - 1; j++)
            val = (xc > mid[j]) ? c[j + 1] : val;
        float lo = val, hi = val;

        // if a midpoint falls in this cell, store (c_lo, c_hi) instead
        #pragma unroll
        for (int j = 0; j < MAX_CB - 1; j++) {
            if (j + 1 < n_cb && cell_of(mid[j]) == cell) {
                lo = c[j];
                hi = c[j + 1];
            }
        }
        __half2 pr = __floats2half2_rn(lo, hi);  // exact: fp16-originated
        unsigned pk = *(unsigned*)&pr;

        // lane-rotated replication: for fixed r, banks are all distinct
        #pragma unroll
        for (int r = 0; r < 32; r++)
            s_tbl[(cell << 5) | ((r + lane) & 31)] = pk;
        __syncthreads();
    }

    // ---------------- phase 2: quantize via LUT, unroll 4 ----------------
    int p = tid;
    for (; p + 3 * stride < n4; p += 4 * stride) {
        float4 v0 = __ldcg(&x[p]);
        float4 v1 = __ldcg(&x[p + stride]);
        float4 v2 = __ldcg(&x[p + 2 * stride]);
        float4 v3 = __ldcg(&x[p + 3 * stride]);
        float4 r0 = quant4(v0, xmin, inv, s_tbl, lane);
        float4 r1 = quant4(v1, xmin, inv, s_tbl, lane);
        float4 r2 = quant4(v2, xmin, inv, s_tbl, lane);
        float4 r3 = quant4(v3, xmin, inv, s_tbl, lane);
        __stcs(&out[p], r0);
        __stcs(&out[p + stride], r1);
        __stcs(&out[p + 2 * stride], r2);
        __stcs(&out[p + 3 * stride], r3);
    }
    for (; p < n4; p += stride) {
        float4 v = __ldcg(&x[p]);
        __stcs(&out[p], quant4(v, xmin, inv, s_tbl, lane));
    }
}

extern "C" void kernel_launch(void* const* d_in, const int* in_sizes, int n_in,
                              void* d_out, int out_size) {
    const float4* x = (const float4*)d_in[0];
    const float* cb = (const float*)d_in[1];
    float4* out = (float4*)d_out;

    int n = in_sizes[0];      // 8388608
    int n_cb = in_sizes[1];   // 14
    if (n_cb > MAX_CB) n_cb = MAX_CB;
    int n4 = n >> 2;

    q4_fused_kernel<<<NBLK, NTHR>>>(x, cb, n_cb, out, n4);
}

// round 13
// speedup vs baseline: 1.1085x; 1.1085x over previous
#include <cuda_runtime.h>
#include <cuda_fp16.h>
#include <math_constants.h>

// ---------------------------------------------------------------------------
// Quantization4bit, single persistent kernel:
//   phase 1: per-block min/max partials (grid-stride, float4 __ldcg, unroll-8
//            front-batched loads for MLP)
//   grid barrier: monotonic counter/epoch (replay-safe)
//   phase 2: affine normalize + nearest-codebook via a 256-cell LUT of
//            half2(c_lo, c_hi), replicated x32 at s[cell*32+lane] (bank==lane,
//            conflict-free for any data), copy-based cheap build. Unroll-8.
//            Midpoint recomputed as 0.5f*(f32(lo)+f32(hi)) -- identical fp32
//            ops/inputs as the reference chain => bit-exact
//            (fp32 |.| argmin, first-min tie-break).
// 592 blocks x 256 thr, 4 blocks/SM co-resident => spin barrier safe.
// ---------------------------------------------------------------------------

#define MAX_CB 16
#define NBLK 592
#define NTHR 256
#define NCELL 256
#define UNR 8

__device__ float g_pmin[NBLK];
__device__ float g_pmax[NBLK];
__device__ float g_final_min;
__device__ float g_final_max;
__device__ unsigned g_counter = 0;   // monotonic arrivals (never reset)
__device__ unsigned g_release = 0;   // monotonic release epoch

__device__ __forceinline__ int cell_of(float xn) {
    float u = fmaf(xn, (float)(NCELL / 2), (float)(NCELL / 2));  // >= 0 by construction
    u = fminf(u, (float)(NCELL - 1));
    return (int)u;
}

__device__ __forceinline__ float lut_pick(unsigned e, float xn) {
    float lo = __half2float(__ushort_as_half((unsigned short)(e & 0xFFFFu)));
    float hi = __half2float(__ushort_as_half((unsigned short)(e >> 16)));
    float mid = 0.5f * (lo + hi);   // exact same computation as reference mid[]
    // strict > : exact-midpoint ties go to the LOWER index,
    // matching argmin's first-minimum tie-break.
    return (xn > mid) ? hi : lo;
}

__device__ __forceinline__ void mm4(float4 v, float& mn, float& mx) {
    mn = fminf(mn, fminf(fminf(v.x, v.y), fminf(v.z, v.w)));
    mx = fmaxf(mx, fmaxf(fmaxf(v.x, v.y), fmaxf(v.z, v.w)));
}

__device__ __forceinline__ float4 quant4(float4 v, float xmin, float inv,
                                         const unsigned* s_tbl, int lane) {
    float a[4] = {v.x, v.y, v.z, v.w};
    float r[4];
    #pragma unroll
    for (int k = 0; k < 4; k++) {
        float xn = fmaf((a[k] - xmin) * inv, 2.0f, -1.0f);
        unsigned e = s_tbl[(cell_of(xn) << 5) | lane];   // bank == lane
        r[k] = lut_pick(e, xn);
    }
    return make_float4(r[0], r[1], r[2], r[3]);
}

__global__ void __launch_bounds__(NTHR, 4)
q4_fused_kernel(const float4* __restrict__ x,
                const float* __restrict__ cb, int n_cb,
                float4* __restrict__ out, int n4) {
    __shared__ unsigned s_tbl[NCELL * 32];   // x32 replicated, bank == lane
    __shared__ float s_red[NTHR / 32];
    __shared__ float s_red2[NTHR / 32];
    __shared__ unsigned s_epoch;
    __shared__ int s_last;

    const int tid = blockIdx.x * NTHR + threadIdx.x;
    const int stride = NBLK * NTHR;
    const int lane = threadIdx.x & 31;
    const int warp = threadIdx.x >> 5;

    // ---------------- phase 1: local min/max (unroll 8, .cg loads) --------
    float lmin = CUDART_INF_F;
    float lmax = -CUDART_INF_F;

    int i = tid;
    for (; i + (UNR - 1) * stride < n4; i += UNR * stride) {
        float4 v[UNR];
        #pragma unroll
        for (int u = 0; u < UNR; u++)
            v[u] = __ldcg(&x[i + u * stride]);
        #pragma unroll
        for (int u = 0; u < UNR; u++)
            mm4(v[u], lmin, lmax);
    }
    for (; i < n4; i += stride) {
        float4 v = __ldcg(&x[i]);
        mm4(v, lmin, lmax);
    }

    #pragma unroll
    for (int o = 16; o > 0; o >>= 1) {
        lmin = fminf(lmin, __shfl_xor_sync(0xFFFFFFFFu, lmin, o));
        lmax = fmaxf(lmax, __shfl_xor_sync(0xFFFFFFFFu, lmax, o));
    }
    if (lane == 0) { s_red[warp] = lmin; s_red2[warp] = lmax; }
    __syncthreads();

    if (threadIdx.x == 0) {
        float bmin = s_red[0], bmax = s_red2[0];
        #pragma unroll
        for (int w = 1; w < NTHR / 32; w++) {
            bmin = fminf(bmin, s_red[w]);
            bmax = fmaxf(bmax, s_red2[w]);
        }
        g_pmin[blockIdx.x] = bmin;
        g_pmax[blockIdx.x] = bmax;
        __threadfence();
        unsigned old = atomicAdd(&g_counter, 1u);
        s_epoch = old / NBLK;
        s_last = ((old % NBLK) == NBLK - 1);
    }
    __syncthreads();

    const unsigned epoch = s_epoch;

    if (s_last) {
        float bmin = CUDART_INF_F, bmax = -CUDART_INF_F;
        for (int j = threadIdx.x; j < NBLK; j += NTHR) {
            bmin = fminf(bmin, g_pmin[j]);
            bmax = fmaxf(bmax, g_pmax[j]);
        }
        #pragma unroll
        for (int o = 16; o > 0; o >>= 1) {
            bmin = fminf(bmin, __shfl_xor_sync(0xFFFFFFFFu, bmin, o));
            bmax = fmaxf(bmax, __shfl_xor_sync(0xFFFFFFFFu, bmax, o));
        }
        if (lane == 0) { s_red[warp] = bmin; s_red2[warp] = bmax; }
        __syncthreads();
        if (threadIdx.x == 0) {
            float fmn = s_red[0], fmx = s_red2[0];
            #pragma unroll
            for (int w = 1; w < NTHR / 32; w++) {
                fmn = fminf(fmn, s_red[w]);
                fmx = fmaxf(fmx, s_red2[w]);
            }
            g_final_min = fmn;
            g_final_max = fmx;
            __threadfence();
            atomicAdd(&g_release, 1u);
        }
        __syncthreads();
    } else {
        if (threadIdx.x == 0) {
            while (*((volatile unsigned*)&g_release) < epoch + 1u)
                __nanosleep(64);
        }
        __syncthreads();
    }
    __threadfence();  // acquire for g_final_min/max

    const float xmin = g_final_min;
    const float xmax = g_final_max;
    const float inv = 1.0f / (xmax - xmin);

    // ------- build the x32-replicated 4B/cell LUT (copy-based, cheap) -----
    {
        float c[MAX_CB];
        #pragma unroll
        for (int k = 0; k < MAX_CB; k++)
            c[k] = (k < n_cb) ? cb[k] : CUDART_INF_F;
        float mid[MAX_CB - 1];
        #pragma unroll
        for (int j = 0; j < MAX_CB - 1; j++)
            mid[j] = (j + 1 < n_cb) ? 0.5f * (c[j] + c[j + 1]) : CUDART_INF_F;

        // each thread owns exactly one cell (NTHR == NCELL)
        int cell = threadIdx.x;
        float xc = ((float)cell + 0.5f) * (2.0f / NCELL) - 1.0f;
        float val = c[0];
        #pragma unroll
        for (int j = 0; j < MAX_CB - 1; j++)
            val = (xc > mid[j]) ? c[j + 1] : val;
        float lo = val, hi = val;

        // if a midpoint falls in this cell, store (c_lo, c_hi) instead
        #pragma unroll
        for (int j = 0; j < MAX_CB - 1; j++) {
            if (j + 1 < n_cb && cell_of(mid[j]) == cell) {
                lo = c[j];
                hi = c[j + 1];
            }
        }
        __half2 pr = __floats2half2_rn(lo, hi);  // exact: fp16-originated
        unsigned pk = *(unsigned*)&pr;

        // lane-rotated replication: for fixed r, banks are all distinct
        #pragma unroll
        for (int r = 0; r < 32; r++)
            s_tbl[(cell << 5) | ((r + lane) & 31)] = pk;
        __syncthreads();
    }

    // ---------------- phase 2: quantize via LUT, unroll 8 ----------------
    int p = tid;
    for (; p + (UNR - 1) * stride < n4; p += UNR * stride) {
        float4 v[UNR];
        #pragma unroll
        for (int u = 0; u < UNR; u++)
            v[u] = __ldcg(&x[p + u * stride]);
        #pragma unroll
        for (int u = 0; u < UNR; u++) {
            float4 r = quant4(v[u], xmin, inv, s_tbl, lane);
            __stcs(&out[p + u * stride], r);
        }
    }
    for (; p < n4; p += stride) {
        float4 v = __ldcg(&x[p]);
        __stcs(&out[p], quant4(v, xmin, inv, s_tbl, lane));
    }
}

extern "C" void kernel_launch(void* const* d_in, const int* in_sizes, int n_in,
                              void* d_out, int out_size) {
    const float4* x = (const float4*)d_in[0];
    const float* cb = (const float*)d_in[1];
    float4* out = (float4*)d_out;

    int n = in_sizes[0];      // 8388608
    int n_cb = in_sizes[1];   // 14
    if (n_cb > MAX_CB) n_cb = MAX_CB;
    int n4 = n >> 2;

    q4_fused_kernel<<<NBLK, NTHR>>>(x, cb, n_cb, out, n4);
}

// round 14
// speedup vs baseline: 1.1235x; 1.0135x over previous
#include <cuda_runtime.h>
#include <cuda_fp16.h>
#include <math_constants.h>

// ---------------------------------------------------------------------------
// Quantization4bit, single persistent kernel:
//   prologue: build the 256-cell LUT (x32-replicated, bank==lane,
//             conflict-free) — depends only on the codebook, so it is built
//             BEFORE phase 1 and overlaps with nothing on the critical path.
//   phase 1:  per-block min/max partials (grid-stride, float4 __ldcg, unroll-4)
//   prefetch: first phase-2 batch loaded BEFORE the barrier spin, so the
//             barrier wait overlaps a memory round-trip.
//   barrier:  monotonic counter/epoch (replay-safe)
//   phase 2:  affine normalize + nearest-codebook via the LUT. Midpoint
//             recomputed as 0.5f*(f32(lo)+f32(hi)) — identical fp32 ops as
//             the reference chain => bit-exact (fp32 |.| argmin, first-min
//             tie-break).
// 592 blocks x 256 thr, 4 blocks/SM co-resident => spin barrier safe.
// ---------------------------------------------------------------------------

#define MAX_CB 16
#define NBLK 592
#define NTHR 256
#define NCELL 256

__device__ float g_pmin[NBLK];
__device__ float g_pmax[NBLK];
__device__ float g_final_min;
__device__ float g_final_max;
__device__ unsigned g_counter = 0;   // monotonic arrivals (never reset)
__device__ unsigned g_release = 0;   // monotonic release epoch

__device__ __forceinline__ int cell_of(float xn) {
    float u = fmaf(xn, (float)(NCELL / 2), (float)(NCELL / 2));  // >= 0 by construction
    u = fminf(u, (float)(NCELL - 1));
    return (int)u;
}

__device__ __forceinline__ float lut_pick(unsigned e, float xn) {
    float lo = __half2float(__ushort_as_half((unsigned short)(e & 0xFFFFu)));
    float hi = __half2float(__ushort_as_half((unsigned short)(e >> 16)));
    float mid = 0.5f * (lo + hi);   // exact same computation as reference mid[]
    // strict > : exact-midpoint ties go to the LOWER index,
    // matching argmin's first-minimum tie-break.
    return (xn > mid) ? hi : lo;
}

__device__ __forceinline__ void mm4(float4 v, float& mn, float& mx) {
    mn = fminf(mn, fminf(fminf(v.x, v.y), fminf(v.z, v.w)));
    mx = fmaxf(mx, fmaxf(fmaxf(v.x, v.y), fmaxf(v.z, v.w)));
}

__device__ __forceinline__ float4 quant4(float4 v, float xmin, float inv,
                                         const unsigned* s_tbl, int lane) {
    float a[4] = {v.x, v.y, v.z, v.w};
    float r[4];
    #pragma unroll
    for (int k = 0; k < 4; k++) {
        float xn = fmaf((a[k] - xmin) * inv, 2.0f, -1.0f);
        unsigned e = s_tbl[(cell_of(xn) << 5) | lane];   // bank == lane
        r[k] = lut_pick(e, xn);
    }
    return make_float4(r[0], r[1], r[2], r[3]);
}

__global__ void __launch_bounds__(NTHR, 4)
q4_fused_kernel(const float4* __restrict__ x,
                const float* __restrict__ cb, int n_cb,
                float4* __restrict__ out, int n4) {
    __shared__ unsigned s_tbl[NCELL * 32];   // x32 replicated, bank == lane
    __shared__ float s_red[NTHR / 32];
    __shared__ float s_red2[NTHR / 32];
    __shared__ unsigned s_epoch;
    __shared__ int s_last;

    const int tid = blockIdx.x * NTHR + threadIdx.x;
    const int stride = NBLK * NTHR;
    const int lane = threadIdx.x & 31;
    const int warp = threadIdx.x >> 5;

    // ------- prologue: build the LUT (codebook-only, no min/max needed) ----
    {
        float c[MAX_CB];
        #pragma unroll
        for (int k = 0; k < MAX_CB; k++)
            c[k] = (k < n_cb) ? cb[k] : CUDART_INF_F;
        float mid[MAX_CB - 1];
        #pragma unroll
        for (int j = 0; j < MAX_CB - 1; j++)
            mid[j] = (j + 1 < n_cb) ? 0.5f * (c[j] + c[j + 1]) : CUDART_INF_F;

        // each thread owns exactly one cell (NTHR == NCELL)
        int cell = threadIdx.x;
        float xc = ((float)cell + 0.5f) * (2.0f / NCELL) - 1.0f;
        float val = c[0];
        #pragma unroll
        for (int j = 0; j < MAX_CB - 1; j++)
            val = (xc > mid[j]) ? c[j + 1] : val;
        float lo = val, hi = val;

        // if a midpoint falls in this cell, store (c_lo, c_hi) instead
        #pragma unroll
        for (int j = 0; j < MAX_CB - 1; j++) {
            if (j + 1 < n_cb && cell_of(mid[j]) == cell) {
                lo = c[j];
                hi = c[j + 1];
            }
        }
        __half2 pr = __floats2half2_rn(lo, hi);  // exact: fp16-originated
        unsigned pk = *(unsigned*)&pr;

        // lane-rotated replication: for fixed r, banks are all distinct
        #pragma unroll
        for (int r = 0; r < 32; r++)
            s_tbl[(cell << 5) | ((r + lane) & 31)] = pk;
    }
    // (visibility of s_tbl is guaranteed by the __syncthreads in the barrier
    //  sequence below, which every thread passes before phase 2)

    // ---------------- phase 1: local min/max (unroll 4, .cg loads) --------
    float lmin = CUDART_INF_F;
    float lmax = -CUDART_INF_F;

    int i = tid;
    for (; i + 3 * stride < n4; i += 4 * stride) {
        float4 v0 = __ldcg(&x[i]);
        float4 v1 = __ldcg(&x[i + stride]);
        float4 v2 = __ldcg(&x[i + 2 * stride]);
        float4 v3 = __ldcg(&x[i + 3 * stride]);
        mm4(v0, lmin, lmax);
        mm4(v1, lmin, lmax);
        mm4(v2, lmin, lmax);
        mm4(v3, lmin, lmax);
    }
    for (; i < n4; i += stride) {
        float4 v = __ldcg(&x[i]);
        mm4(v, lmin, lmax);
    }

    #pragma unroll
    for (int o = 16; o > 0; o >>= 1) {
        lmin = fminf(lmin, __shfl_xor_sync(0xFFFFFFFFu, lmin, o));
        lmax = fmaxf(lmax, __shfl_xor_sync(0xFFFFFFFFu, lmax, o));
    }
    if (lane == 0) { s_red[warp] = lmin; s_red2[warp] = lmax; }

    // ------- prefetch first phase-2 batch (independent of the barrier) ----
    float4 vp0, vp1, vp2, vp3;
    bool has_pre = (tid + 3 * stride < n4);
    if (has_pre) {
        vp0 = __ldcg(&x[tid]);
        vp1 = __ldcg(&x[tid + stride]);
        vp2 = __ldcg(&x[tid + 2 * stride]);
        vp3 = __ldcg(&x[tid + 3 * stride]);
    }

    __syncthreads();

    if (threadIdx.x == 0) {
        float bmin = s_red[0], bmax = s_red2[0];
        #pragma unroll
        for (int w = 1; w < NTHR / 32; w++) {
            bmin = fminf(bmin, s_red[w]);
            bmax = fmaxf(bmax, s_red2[w]);
        }
        g_pmin[blockIdx.x] = bmin;
        g_pmax[blockIdx.x] = bmax;
        __threadfence();
        unsigned old = atomicAdd(&g_counter, 1u);
        s_epoch = old / NBLK;
        s_last = ((old % NBLK) == NBLK - 1);
    }
    __syncthreads();

    const unsigned epoch = s_epoch;

    if (s_last) {
        float bmin = CUDART_INF_F, bmax = -CUDART_INF_F;
        for (int j = threadIdx.x; j < NBLK; j += NTHR) {
            bmin = fminf(bmin, g_pmin[j]);
            bmax = fmaxf(bmax, g_pmax[j]);
        }
        #pragma unroll
        for (int o = 16; o > 0; o >>= 1) {
            bmin = fminf(bmin, __shfl_xor_sync(0xFFFFFFFFu, bmin, o));
            bmax = fmaxf(bmax, __shfl_xor_sync(0xFFFFFFFFu, bmax, o));
        }
        if (lane == 0) { s_red[warp] = bmin; s_red2[warp] = bmax; }
        __syncthreads();
        if (threadIdx.x == 0) {
            float fmn = s_red[0], fmx = s_red2[0];
            #pragma unroll
            for (int w = 1; w < NTHR / 32; w++) {
                fmn = fminf(fmn, s_red[w]);
                fmx = fmaxf(fmx, s_red2[w]);
            }
            g_final_min = fmn;
            g_final_max = fmx;
            __threadfence();
            atomicAdd(&g_release, 1u);
        }
        __syncthreads();
    } else {
        if (threadIdx.x == 0) {
            while (*((volatile unsigned*)&g_release) < epoch + 1u)
                __nanosleep(64);
        }
        __syncthreads();
    }
    __threadfence();  // acquire for g_final_min/max

    const float xmin = g_final_min;
    const float xmax = g_final_max;
    const float inv = 1.0f / (xmax - xmin);

    // ---------------- phase 2: quantize via LUT, unroll 4 ----------------
    int p = tid;

    // consume the prefetched batch first
    if (has_pre) {
        __stcs(&out[p], quant4(vp0, xmin, inv, s_tbl, lane));
        __stcs(&out[p + stride], quant4(vp1, xmin, inv, s_tbl, lane));
        __stcs(&out[p + 2 * stride], quant4(vp2, xmin, inv, s_tbl, lane));
        __stcs(&out[p + 3 * stride], quant4(vp3, xmin, inv, s_tbl, lane));
        p += 4 * stride;
    }

    for (; p + 3 * stride < n4; p += 4 * stride) {
        float4 v0 = __ldcg(&x[p]);
        float4 v1 = __ldcg(&x[p + stride]);
        float4 v2 = __ldcg(&x[p + 2 * stride]);
        float4 v3 = __ldcg(&x[p + 3 * stride]);
        float4 r0 = quant4(v0, xmin, inv, s_tbl, lane);
        float4 r1 = quant4(v1, xmin, inv, s_tbl, lane);
        float4 r2 = quant4(v2, xmin, inv, s_tbl, lane);
        float4 r3 = quant4(v3, xmin, inv, s_tbl, lane);
        __stcs(&out[p], r0);
        __stcs(&out[p + stride], r1);
        __stcs(&out[p + 2 * stride], r2);
        __stcs(&out[p + 3 * stride], r3);
    }
    for (; p < n4; p += stride) {
        float4 v = __ldcg(&x[p]);
        __stcs(&out[p], quant4(v, xmin, inv, s_tbl, lane));
    }
}

extern "C" void kernel_launch(void* const* d_in, const int* in_sizes, int n_in,
                              void* d_out, int out_size) {
    const float4* x = (const float4*)d_in[0];
    const float* cb = (const float*)d_in[1];
    float4* out = (float4*)d_out;

    int n = in_sizes[0];      // 8388608
    int n_cb = in_sizes[1];   // 14
    if (n_cb > MAX_CB) n_cb = MAX_CB;
    int n4 = n >> 2;

    q4_fused_kernel<<<NBLK, NTHR>>>(x, cb, n_cb, out, n4);
}